// round 16
// baseline (speedup 1.0000x reference)
#include <cuda_runtime.h>
#include <cuda_bf16.h>
#include <cstdint>

#define N_NODES 50000
#define N_EDGES 400000
#define DIM     128
#define GTHREADS 512
#define GBLOCKS  ((N_NODES + 127) / 128)     // 391

#define TSTRIDE 136                          // bf16/row: 272B = 4-bank shift, LDSM conflict-free
#define TILE_ELEMS (128 * TSTRIDE)
#define LO_OFF (TILE_ELEMS * 2)              // byte offset hi-tile -> lo-tile
#define SMEM_SZ (4 * TILE_ELEMS * 2)         // Ah, Al, Bh, Bl  = 139264 B

#define SLOT_CAP 96                          // Poisson(8) max degree << 96

// ---- scratch (no allocations allowed) ----
__device__ float g_h  [(size_t)N_NODES * DIM];
__device__ int   g_is64;
__device__ __nv_bfloat16 g_wimg[2][2 * TILE_ELEMS];
__device__ int g_cnt  [N_NODES];
__device__ int g_slots[(size_t)N_NODES * SLOT_CAP];

// ---------------------------------------------------------------------------
__device__ __forceinline__ uint32_t smem_u32(const void* p) {
    uint32_t a;
    asm("{ .reg .u64 t; cvta.to.shared.u64 t, %1; cvt.u32.u64 %0, t; }"
        : "=r"(a) : "l"(p));
    return a;
}

#define LDSM_X4(r0, r1, r2, r3, a)                                             \
    asm volatile("ldmatrix.sync.aligned.m8n8.x4.shared.b16 {%0,%1,%2,%3}, [%4];" \
                 : "=r"(r0), "=r"(r1), "=r"(r2), "=r"(r3) : "r"(a))

#define MMA_BF16(d, a0, a1, a2, a3, b0, b1)                                    \
    asm volatile("mma.sync.aligned.m16n8k16.row.col.f32.bf16.bf16.f32 "        \
                 "{%0,%1,%2,%3}, {%4,%5,%6,%7}, {%8,%9}, {%0,%1,%2,%3};"       \
                 : "+f"((d).x), "+f"((d).y), "+f"((d).z), "+f"((d).w)          \
                 : "r"(a0), "r"(a1), "r"(a2), "r"(a3), "r"(b0), "r"(b1))

__device__ __forceinline__ void split2(float f0, float f1, uint32_t& hp, uint32_t& lp) {
    __nv_bfloat16 h0 = __float2bfloat16_rn(f0);
    __nv_bfloat16 h1 = __float2bfloat16_rn(f1);
    __nv_bfloat16 l0 = __float2bfloat16_rn(f0 - __bfloat162float(h0));
    __nv_bfloat16 l1 = __float2bfloat16_rn(f1 - __bfloat162float(h1));
    hp = (uint32_t)__bfloat16_as_ushort(h1) << 16 | __bfloat16_as_ushort(h0);
    lp = (uint32_t)__bfloat16_as_ushort(l1) << 16 | __bfloat16_as_ushort(l0);
}

// ---------------------------------------------------------------------------
// Setup: blockIdx partitions work — detect dtype | zero g_cnt | prep W images
//   block 0, thread 0: detect
//   blocks [1, 1+196): zero g_cnt
//   blocks [197, 197+64): W hi/lo image prep (2 layers x 8192 pairs)
// ---------------------------------------------------------------------------
#define ZB   ((N_NODES + 255) / 256)         // 196
#define WB   (2 * (DIM * DIM / 2) / 256)     // 64
#define SETUP_BLOCKS (1 + ZB + WB)           // 261

__global__ void setup_kernel(const void* eiv,
                             const float* __restrict__ W1,
                             const float* __restrict__ W2)
{
    const int b = blockIdx.x, tid = threadIdx.x;
    if (b == 0) {
        if (tid == 0) {
            const long long* p = (const long long*)eiv;
            int ok64 = 1;
            for (int i = 0; i < 64; ++i) {
                long long v = p[i];
                if (v < 0 || v >= N_NODES) { ok64 = 0; break; }
            }
            g_is64 = ok64;
        }
        return;
    }
    if (b < 1 + ZB) {
        int i = (b - 1) * 256 + tid;
        if (i < N_NODES) g_cnt[i] = 0;
        return;
    }
    {
        int idx = (b - 1 - ZB) * 256 + tid;        // 0..16383
        int layer = idx >> 13;                      // 0/1
        int j = idx & 8191;                         // pair index within layer
        const float* W = layer ? W2 : W1;
        __nv_bfloat16* img = g_wimg[layer];
        int c = j >> 6;
        int k = (j & 63) * 2;
        float f0 = W[c * DIM + k], f1 = W[c * DIM + k + 1];
        uint32_t hp, lp;
        split2(f0, f1, hp, lp);
        *(uint32_t*)&img[c * TSTRIDE + k]              = hp;
        *(uint32_t*)&img[TILE_ELEMS + c * TSTRIDE + k] = lp;
    }
}

// ---------------------------------------------------------------------------
// Fill fixed-stride buckets, 4 edges per thread for ILP (latency-bound kernel)
// ---------------------------------------------------------------------------
__global__ void __launch_bounds__(256)
fill_kernel(const void* __restrict__ eiv)
{
    const int e0 = (blockIdx.x * blockDim.x + threadIdx.x) * 4;
    const int is64 = g_is64;
    int s[4], d[4];
    #pragma unroll
    for (int i = 0; i < 4; ++i) {
        int e = e0 + i;
        if (e < N_EDGES) {
            if (is64) {
                long long ls = __ldg((const long long*)eiv + e);
                long long ld = __ldg((const long long*)eiv + N_EDGES + e);
                s[i] = ((unsigned long long)ls < N_NODES) ? (int)ls : -1;
                d[i] = ((unsigned long long)ld < N_NODES) ? (int)ld : -1;
            } else {
                int ls = __ldg((const int*)eiv + e);
                int ld = __ldg((const int*)eiv + N_EDGES + e);
                s[i] = ((unsigned)ls < N_NODES) ? ls : -1;
                d[i] = ((unsigned)ld < N_NODES) ? ld : -1;
            }
        } else { s[i] = -1; d[i] = -1; }
    }
    #pragma unroll
    for (int i = 0; i < 4; ++i) {
        if (s[i] >= 0 && d[i] >= 0) {
            int pos = atomicAdd(&g_cnt[d[i]], 1);
            if (pos < SLOT_CAP)
                g_slots[(size_t)d[i] * SLOT_CAP + pos] = s[i];
        }
    }
}

// ---------------------------------------------------------------------------
// Tensor-core GEMM tile (mma.sync bf16, fp32 acc):
//   Y[128,128] = act( Z[128,128] @ W^T + b )
// fp32 emulated: Z W^T ~= Zh Wh + Zh Wl + Zl Wh
// FIRST:  Z = x -> Y = g_h (relu)
// !FIRST: Z = h + mean_{s in bucket(n)} h[s]  (gather FUSED into A-fill) -> out
// ---------------------------------------------------------------------------
template<bool FIRST>
__global__ void __launch_bounds__(GTHREADS, 1)
gemm_mma_kernel(const float* __restrict__ Zext,
                const float* __restrict__ Wimg,
                const float* __restrict__ bias,
                float* __restrict__ Yext)
{
    extern __shared__ __align__(16) __nv_bfloat16 smem[];
    __nv_bfloat16* Ah = smem;                       // [+TILE_ELEMS] = Al
    __nv_bfloat16* Bh = smem + 2 * TILE_ELEMS;      // [+TILE_ELEMS] = Bl

    const float* Z = FIRST ? Zext : g_h;
    float*       Y = FIRST ? g_h  : Yext;
    const int tid = threadIdx.x;
    const int wid = tid >> 5, lane = tid & 31;
    const int row_base = blockIdx.x * 128;

    // ---- B tiles: coalesced copy of the preconverted image ----
    {
        const uint4* src = (const uint4*)Wimg;
        uint4* dst = (uint4*)Bh;
        #pragma unroll
        for (int i = tid; i < 2 * TILE_ELEMS * 2 / 16; i += GTHREADS)
            dst[i] = src[i];
    }

    // ---- A tiles: warp w fills rows 8w..8w+7, lane l covers cols 4l..4l+3 ----
    {
        uint32_t* ahp = (uint32_t*)Ah;
        uint32_t* alp = (uint32_t*)(Ah + TILE_ELEMS);
        #pragma unroll
        for (int rr = 0; rr < 8; ++rr) {
            const int r  = wid * 8 + rr;
            const int gr = row_base + r;
            float4 v = make_float4(0.f, 0.f, 0.f, 0.f);
            if (gr < N_NODES) {
                v = *(const float4*)(Z + (size_t)gr * DIM + lane * 4);
                if (!FIRST) {
                    // fused bucket gather: mean of neighbor h rows
                    int cnt = g_cnt[gr];
                    if (cnt > SLOT_CAP) cnt = SLOT_CAP;
                    const int* slots = g_slots + (size_t)gr * SLOT_CAP;
                    const float* hb = g_h + lane * 4;
                    float4 acc = make_float4(0.f, 0.f, 0.f, 0.f);
                    int j = 0;
                    for (; j + 3 < cnt; j += 4) {        // 4-way MLP
                        int s0 = __ldg(slots + j),     s1 = __ldg(slots + j + 1);
                        int s2 = __ldg(slots + j + 2), s3 = __ldg(slots + j + 3);
                        float4 a0 = *(const float4*)(hb + (size_t)s0 * DIM);
                        float4 a1 = *(const float4*)(hb + (size_t)s1 * DIM);
                        float4 a2 = *(const float4*)(hb + (size_t)s2 * DIM);
                        float4 a3 = *(const float4*)(hb + (size_t)s3 * DIM);
                        acc.x += (a0.x + a1.x) + (a2.x + a3.x);
                        acc.y += (a0.y + a1.y) + (a2.y + a3.y);
                        acc.z += (a0.z + a1.z) + (a2.z + a3.z);
                        acc.w += (a0.w + a1.w) + (a2.w + a3.w);
                    }
                    for (; j < cnt; ++j) {
                        int s0 = __ldg(slots + j);
                        float4 a0 = *(const float4*)(hb + (size_t)s0 * DIM);
                        acc.x += a0.x; acc.y += a0.y; acc.z += a0.z; acc.w += a0.w;
                    }
                    const float inv = 1.0f / fmaxf((float)cnt, 1.0f);
                    v.x += acc.x * inv; v.y += acc.y * inv;
                    v.z += acc.z * inv; v.w += acc.w * inv;
                }
            }
            uint32_t h0, l0, h1, l1;
            split2(v.x, v.y, h0, l0);
            split2(v.z, v.w, h1, l1);
            const int wo = (r * TSTRIDE + lane * 4) >> 1;
            ahp[wo] = h0; ahp[wo + 1] = h1;
            alp[wo] = l0; alp[wo + 1] = l1;
        }
    }
    __syncthreads();

    // ---- mainloop: warp (mw, nw) computes m32 x n32 ----
    const int mw = wid & 3, nw = wid >> 2;
    const int m0 = mw * 32, n0 = nw * 32;

    const int a_row    = m0 + (lane & 15);
    const int a_coloff = (lane >> 4) * 8;
    const int b_row    = n0 + (lane & 7) + ((lane & 16) ? 8 : 0);
    const int b_coloff = ((lane >> 3) & 1) * 8;

    const uint32_t a0b = smem_u32(Ah + a_row * TSTRIDE + a_coloff);
    const uint32_t a1b = a0b + 16 * TSTRIDE * 2;
    const uint32_t b0b = smem_u32(Bh + b_row * TSTRIDE + b_coloff);
    const uint32_t b1b = b0b + 16 * TSTRIDE * 2;

    float4 acc[8];
    #pragma unroll
    for (int i = 0; i < 8; ++i) acc[i] = make_float4(0.f, 0.f, 0.f, 0.f);

    #pragma unroll 2
    for (int ks = 0; ks < 8; ++ks) {
        const uint32_t ko = ks * 32;
        uint32_t ah0, ah1, ah2, ah3, ah4, ah5, ah6, ah7;
        uint32_t al0, al1, al2, al3, al4, al5, al6, al7;
        uint32_t bh0, bh1, bh2, bh3, bh4, bh5, bh6, bh7;
        uint32_t bl0, bl1, bl2, bl3, bl4, bl5, bl6, bl7;
        LDSM_X4(ah0, ah1, ah2, ah3, a0b + ko);
        LDSM_X4(ah4, ah5, ah6, ah7, a1b + ko);
        LDSM_X4(bh0, bh1, bh2, bh3, b0b + ko);
        LDSM_X4(bh4, bh5, bh6, bh7, b1b + ko);
        LDSM_X4(al0, al1, al2, al3, a0b + LO_OFF + ko);
        LDSM_X4(al4, al5, al6, al7, a1b + LO_OFF + ko);
        LDSM_X4(bl0, bl1, bl2, bl3, b0b + LO_OFF + ko);
        LDSM_X4(bl4, bl5, bl6, bl7, b1b + LO_OFF + ko);

        MMA_BF16(acc[0], ah0, ah1, ah2, ah3, bh0, bh1);
        MMA_BF16(acc[1], ah0, ah1, ah2, ah3, bh2, bh3);
        MMA_BF16(acc[2], ah0, ah1, ah2, ah3, bh4, bh5);
        MMA_BF16(acc[3], ah0, ah1, ah2, ah3, bh6, bh7);
        MMA_BF16(acc[4], ah4, ah5, ah6, ah7, bh0, bh1);
        MMA_BF16(acc[5], ah4, ah5, ah6, ah7, bh2, bh3);
        MMA_BF16(acc[6], ah4, ah5, ah6, ah7, bh4, bh5);
        MMA_BF16(acc[7], ah4, ah5, ah6, ah7, bh6, bh7);

        MMA_BF16(acc[0], al0, al1, al2, al3, bh0, bh1);
        MMA_BF16(acc[1], al0, al1, al2, al3, bh2, bh3);
        MMA_BF16(acc[2], al0, al1, al2, al3, bh4, bh5);
        MMA_BF16(acc[3], al0, al1, al2, al3, bh6, bh7);
        MMA_BF16(acc[4], al4, al5, al6, al7, bh0, bh1);
        MMA_BF16(acc[5], al4, al5, al6, al7, bh2, bh3);
        MMA_BF16(acc[6], al4, al5, al6, al7, bh4, bh5);
        MMA_BF16(acc[7], al4, al5, al6, al7, bh6, bh7);

        MMA_BF16(acc[0], ah0, ah1, ah2, ah3, bl0, bl1);
        MMA_BF16(acc[1], ah0, ah1, ah2, ah3, bl2, bl3);
        MMA_BF16(acc[2], ah0, ah1, ah2, ah3, bl4, bl5);
        MMA_BF16(acc[3], ah0, ah1, ah2, ah3, bl6, bl7);
        MMA_BF16(acc[4], ah4, ah5, ah6, ah7, bl0, bl1);
        MMA_BF16(acc[5], ah4, ah5, ah6, ah7, bl2, bl3);
        MMA_BF16(acc[6], ah4, ah5, ah6, ah7, bl4, bl5);
        MMA_BF16(acc[7], ah4, ah5, ah6, ah7, bl6, bl7);
    }

    // ---- epilogue ----
    {
        const int g  = lane >> 2;
        const int qi = lane & 3;
        #pragma unroll
        for (int i = 0; i < 2; ++i) {
            const int orow0 = row_base + m0 + i * 16 + g;
            const int orow1 = orow0 + 8;
            #pragma unroll
            for (int j = 0; j < 4; ++j) {
                const int col = n0 + j * 8 + qi * 2;
                const float4 a = acc[i * 4 + j];
                float2 bb = *(const float2*)(bias + col);
                float2 v0 = make_float2(a.x + bb.x, a.y + bb.y);
                float2 v1 = make_float2(a.z + bb.x, a.w + bb.y);
                if (FIRST) {
                    v0.x = fmaxf(v0.x, 0.f); v0.y = fmaxf(v0.y, 0.f);
                    v1.x = fmaxf(v1.x, 0.f); v1.y = fmaxf(v1.y, 0.f);
                }
                if (orow0 < N_NODES) *(float2*)(Y + (size_t)orow0 * DIM + col) = v0;
                if (orow1 < N_NODES) *(float2*)(Y + (size_t)orow1 * DIM + col) = v1;
            }
        }
    }
}

// ---------------------------------------------------------------------------
extern "C" void kernel_launch(void* const* d_in, const int* in_sizes, int n_in,
                              void* d_out, int out_size)
{
    const float* x  = (const float*)d_in[0];
    const void*  ei = d_in[1];
    const float* W1 = (const float*)d_in[2];
    const float* b1 = (const float*)d_in[3];
    const float* W2 = (const float*)d_in[4];
    const float* b2 = (const float*)d_in[5];
    float*       out = (float*)d_out;

    cudaFuncSetAttribute(gemm_mma_kernel<true>,
                         cudaFuncAttributeMaxDynamicSharedMemorySize, SMEM_SZ);
    cudaFuncSetAttribute(gemm_mma_kernel<false>,
                         cudaFuncAttributeMaxDynamicSharedMemorySize, SMEM_SZ);

    __nv_bfloat16* wimg_d = nullptr;
    cudaGetSymbolAddress((void**)&wimg_d, g_wimg);
    const float* wimg0 = (const float*)wimg_d;
    const float* wimg1 = (const float*)(wimg_d + 2 * TILE_ELEMS);

    // 0) setup: detect dtype + zero counts + W image prep (single launch)
    setup_kernel<<<SETUP_BLOCKS, 256>>>(ei, W1, W2);
    // 1) bucket fill (4 edges/thread)
    fill_kernel<<<(N_EDGES / 4 + 255) / 256, 256>>>(ei);
    // 2) h = relu(x W1^T + b1)
    gemm_mma_kernel<true><<<GBLOCKS, GTHREADS, SMEM_SZ>>>(x, wimg0, b1, nullptr);
    // 3) out = (h + mean neighbor h) W2^T + b2  (gather fused into A-fill)
    gemm_mma_kernel<false><<<GBLOCKS, GTHREADS, SMEM_SZ>>>(nullptr, wimg1, b2, out);
}

// round 17
// speedup vs baseline: 1.0848x; 1.0848x over previous
#include <cuda_runtime.h>
#include <cuda_bf16.h>
#include <cstdint>

#define N_NODES 50000
#define N_EDGES 400000
#define DIM     128
#define GTHREADS 256                         // 8 warps
#define MTILE   64
#define GBLOCKS  ((N_NODES + MTILE - 1) / MTILE)   // 782

#define TSTRIDE 136                          // bf16/row: 272B = 4-bank shift, LDSM conflict-free
#define WTILE_ELEMS (128 * TSTRIDE)          // W image tile (hi or lo), 128 rows
#define A_ELEMS (MTILE * TSTRIDE)            // A tile, 64 rows
#define LO_A (A_ELEMS * 2)                   // byte offset Ah -> Al
#define LO_B (WTILE_ELEMS * 2)               // byte offset Bh -> Bl
#define SMEM_SZ ((2 * A_ELEMS + 2 * WTILE_ELEMS) * 2)   // 104448 B -> 2 CTAs/SM

#define SLOT_CAP 96                          // Poisson(8) max degree << 96

// ---- scratch (no allocations allowed) ----
__device__ float g_h  [(size_t)N_NODES * DIM];
__device__ float g_agg[(size_t)N_NODES * DIM];   // neighbor MEAN of h rows
__device__ int   g_is64;
__device__ __nv_bfloat16 g_wimg[2][2 * WTILE_ELEMS];
__device__ int g_cnt  [N_NODES];
__device__ int g_slots[(size_t)N_NODES * SLOT_CAP];

// ---------------------------------------------------------------------------
__device__ __forceinline__ uint32_t smem_u32(const void* p) {
    uint32_t a;
    asm("{ .reg .u64 t; cvta.to.shared.u64 t, %1; cvt.u32.u64 %0, t; }"
        : "=r"(a) : "l"(p));
    return a;
}

#define LDSM_X4(r0, r1, r2, r3, a)                                             \
    asm volatile("ldmatrix.sync.aligned.m8n8.x4.shared.b16 {%0,%1,%2,%3}, [%4];" \
                 : "=r"(r0), "=r"(r1), "=r"(r2), "=r"(r3) : "r"(a))

#define MMA_BF16(d, a0, a1, a2, a3, b0, b1)                                    \
    asm volatile("mma.sync.aligned.m16n8k16.row.col.f32.bf16.bf16.f32 "        \
                 "{%0,%1,%2,%3}, {%4,%5,%6,%7}, {%8,%9}, {%0,%1,%2,%3};"       \
                 : "+f"((d).x), "+f"((d).y), "+f"((d).z), "+f"((d).w)          \
                 : "r"(a0), "r"(a1), "r"(a2), "r"(a3), "r"(b0), "r"(b1))

__device__ __forceinline__ void split2(float f0, float f1, uint32_t& hp, uint32_t& lp) {
    __nv_bfloat16 h0 = __float2bfloat16_rn(f0);
    __nv_bfloat16 h1 = __float2bfloat16_rn(f1);
    __nv_bfloat16 l0 = __float2bfloat16_rn(f0 - __bfloat162float(h0));
    __nv_bfloat16 l1 = __float2bfloat16_rn(f1 - __bfloat162float(h1));
    hp = (uint32_t)__bfloat16_as_ushort(h1) << 16 | __bfloat16_as_ushort(h0);
    lp = (uint32_t)__bfloat16_as_ushort(l1) << 16 | __bfloat16_as_ushort(l0);
}

// ---------------------------------------------------------------------------
// Setup: blockIdx partitions work — detect dtype | zero g_cnt | prep W images
// ---------------------------------------------------------------------------
#define ZB   ((N_NODES + 255) / 256)         // 196
#define WB   (2 * (DIM * DIM / 2) / 256)     // 64
#define SETUP_BLOCKS (1 + ZB + WB)           // 261

__global__ void setup_kernel(const void* eiv,
                             const float* __restrict__ W1,
                             const float* __restrict__ W2)
{
    const int b = blockIdx.x, tid = threadIdx.x;
    if (b == 0) {
        if (tid == 0) {
            const long long* p = (const long long*)eiv;
            int ok64 = 1;
            for (int i = 0; i < 64; ++i) {
                long long v = p[i];
                if (v < 0 || v >= N_NODES) { ok64 = 0; break; }
            }
            g_is64 = ok64;
        }
        return;
    }
    if (b < 1 + ZB) {
        int i = (b - 1) * 256 + tid;
        if (i < N_NODES) g_cnt[i] = 0;
        return;
    }
    {
        int idx = (b - 1 - ZB) * 256 + tid;        // 0..16383
        int layer = idx >> 13;
        int j = idx & 8191;
        const float* W = layer ? W2 : W1;
        __nv_bfloat16* img = g_wimg[layer];
        int c = j >> 6;
        int k = (j & 63) * 2;
        float f0 = W[c * DIM + k], f1 = W[c * DIM + k + 1];
        uint32_t hp, lp;
        split2(f0, f1, hp, lp);
        *(uint32_t*)&img[c * TSTRIDE + k]               = hp;
        *(uint32_t*)&img[WTILE_ELEMS + c * TSTRIDE + k] = lp;
    }
}

// ---------------------------------------------------------------------------
// Fill fixed-stride buckets, 4 edges per thread for ILP
// ---------------------------------------------------------------------------
__global__ void __launch_bounds__(256)
fill_kernel(const void* __restrict__ eiv)
{
    const int e0 = (blockIdx.x * blockDim.x + threadIdx.x) * 4;
    const int is64 = g_is64;
    int s[4], d[4];
    #pragma unroll
    for (int i = 0; i < 4; ++i) {
        int e = e0 + i;
        if (e < N_EDGES) {
            if (is64) {
                long long ls = __ldg((const long long*)eiv + e);
                long long ld = __ldg((const long long*)eiv + N_EDGES + e);
                s[i] = ((unsigned long long)ls < N_NODES) ? (int)ls : -1;
                d[i] = ((unsigned long long)ld < N_NODES) ? (int)ld : -1;
            } else {
                int ls = __ldg((const int*)eiv + e);
                int ld = __ldg((const int*)eiv + N_EDGES + e);
                s[i] = ((unsigned)ls < N_NODES) ? ls : -1;
                d[i] = ((unsigned)ld < N_NODES) ? ld : -1;
            }
        } else { s[i] = -1; d[i] = -1; }
    }
    #pragma unroll
    for (int i = 0; i < 4; ++i) {
        if (s[i] >= 0 && d[i] >= 0) {
            int pos = atomicAdd(&g_cnt[d[i]], 1);
            if (pos < SLOT_CAP)
                g_slots[(size_t)d[i] * SLOT_CAP + pos] = s[i];
        }
    }
}

// ---------------------------------------------------------------------------
// Gather: warp per node, HIGH occupancy (latency-bound work lives here).
// ---------------------------------------------------------------------------
__global__ void __launch_bounds__(256)
gather_kernel() {
    const int n    = (blockIdx.x * blockDim.x + threadIdx.x) >> 5;
    const int lane = threadIdx.x & 31;
    if (n >= N_NODES) return;
    int cnt = g_cnt[n];
    if (cnt > SLOT_CAP) cnt = SLOT_CAP;
    const int* slots = g_slots + (size_t)n * SLOT_CAP;

    float4 v = make_float4(0.f, 0.f, 0.f, 0.f);
    const float* hb = g_h + lane * 4;
    int j = 0;
    for (; j + 3 < cnt; j += 4) {                    // 4-way MLP
        int s0 = __ldg(slots + j),     s1 = __ldg(slots + j + 1);
        int s2 = __ldg(slots + j + 2), s3 = __ldg(slots + j + 3);
        float4 a0 = *(const float4*)(hb + (size_t)s0 * DIM);
        float4 a1 = *(const float4*)(hb + (size_t)s1 * DIM);
        float4 a2 = *(const float4*)(hb + (size_t)s2 * DIM);
        float4 a3 = *(const float4*)(hb + (size_t)s3 * DIM);
        v.x += (a0.x + a1.x) + (a2.x + a3.x);
        v.y += (a0.y + a1.y) + (a2.y + a3.y);
        v.z += (a0.z + a1.z) + (a2.z + a3.z);
        v.w += (a0.w + a1.w) + (a2.w + a3.w);
    }
    for (; j < cnt; ++j) {
        int s0 = __ldg(slots + j);
        float4 a = *(const float4*)(hb + (size_t)s0 * DIM);
        v.x += a.x; v.y += a.y; v.z += a.z; v.w += a.w;
    }
    const float inv = 1.0f / fmaxf((float)cnt, 1.0f);
    *(float4*)(g_agg + (size_t)n * DIM + lane * 4) =
        make_float4(v.x * inv, v.y * inv, v.z * inv, v.w * inv);
}

// ---------------------------------------------------------------------------
// Tensor-core GEMM tile (mma.sync bf16, fp32 acc): Y[64,128] per CTA.
// fp32 emulated: Z W^T ~= Zh Wh + Zh Wl + Zl Wh
// 8 warps in 2x4 grid; warp = m32 x n32 -> 8 float4 accumulators.
// 104KB smem -> 2 CTAs/SM (double the warps of the 128-row version).
// ---------------------------------------------------------------------------
template<bool FIRST>
__global__ void __launch_bounds__(GTHREADS, 2)
gemm_mma_kernel(const float* __restrict__ Zext,
                const float* __restrict__ Wimg,
                const float* __restrict__ bias,
                float* __restrict__ Yext)
{
    extern __shared__ __align__(16) __nv_bfloat16 smem[];
    __nv_bfloat16* Ah = smem;                        // [+A_ELEMS] = Al
    __nv_bfloat16* Bh = smem + 2 * A_ELEMS;          // [+WTILE_ELEMS] = Bl

    const float* Z = FIRST ? Zext : g_h;
    float*       Y = FIRST ? g_h  : Yext;
    const int tid = threadIdx.x;
    const int wid = tid >> 5, lane = tid & 31;
    const int row_base = blockIdx.x * MTILE;

    // ---- B tiles: coalesced copy of the preconverted image (hi+lo) ----
    {
        const uint4* src = (const uint4*)Wimg;
        uint4* dst = (uint4*)Bh;
        #pragma unroll
        for (int i = tid; i < 2 * WTILE_ELEMS * 2 / 16; i += GTHREADS)
            dst[i] = src[i];
    }

    // ---- A tiles: warp w fills rows 8w..8w+7, lane l covers cols 4l..4l+3 ----
    {
        uint32_t* ahp = (uint32_t*)Ah;
        uint32_t* alp = (uint32_t*)(Ah + A_ELEMS);
        #pragma unroll
        for (int rr = 0; rr < 8; ++rr) {
            const int r  = wid * 8 + rr;
            const int gr = row_base + r;
            float4 v = make_float4(0.f, 0.f, 0.f, 0.f);
            if (gr < N_NODES) {
                v = *(const float4*)(Z + (size_t)gr * DIM + lane * 4);
                if (!FIRST) {       // g_agg already holds the neighbor MEAN
                    float4 a = *(const float4*)(g_agg + (size_t)gr * DIM + lane * 4);
                    v.x += a.x; v.y += a.y; v.z += a.z; v.w += a.w;
                }
            }
            uint32_t h0, l0, h1, l1;
            split2(v.x, v.y, h0, l0);
            split2(v.z, v.w, h1, l1);
            const int wo = (r * TSTRIDE + lane * 4) >> 1;
            ahp[wo] = h0; ahp[wo + 1] = h1;
            alp[wo] = l0; alp[wo + 1] = l1;
        }
    }
    __syncthreads();

    // ---- mainloop: warp (mw, nw) computes m32 x n32 ----
    const int mw = wid & 1, nw = wid >> 1;
    const int m0 = mw * 32, n0 = nw * 32;

    const int a_row    = m0 + (lane & 15);
    const int a_coloff = (lane >> 4) * 8;
    const int b_row    = n0 + (lane & 7) + ((lane & 16) ? 8 : 0);
    const int b_coloff = ((lane >> 3) & 1) * 8;

    const uint32_t a0b = smem_u32(Ah + a_row * TSTRIDE + a_coloff);
    const uint32_t a1b = a0b + 16 * TSTRIDE * 2;
    const uint32_t b0b = smem_u32(Bh + b_row * TSTRIDE + b_coloff);
    const uint32_t b1b = b0b + 16 * TSTRIDE * 2;

    float4 acc[8];
    #pragma unroll
    for (int i = 0; i < 8; ++i) acc[i] = make_float4(0.f, 0.f, 0.f, 0.f);

    #pragma unroll 2
    for (int ks = 0; ks < 8; ++ks) {
        const uint32_t ko = ks * 32;
        uint32_t ah0, ah1, ah2, ah3, ah4, ah5, ah6, ah7;
        uint32_t al0, al1, al2, al3, al4, al5, al6, al7;
        uint32_t bh0, bh1, bh2, bh3, bh4, bh5, bh6, bh7;
        uint32_t bl0, bl1, bl2, bl3, bl4, bl5, bl6, bl7;
        LDSM_X4(ah0, ah1, ah2, ah3, a0b + ko);
        LDSM_X4(ah4, ah5, ah6, ah7, a1b + ko);
        LDSM_X4(bh0, bh1, bh2, bh3, b0b + ko);
        LDSM_X4(bh4, bh5, bh6, bh7, b1b + ko);
        LDSM_X4(al0, al1, al2, al3, a0b + LO_A + ko);
        LDSM_X4(al4, al5, al6, al7, a1b + LO_A + ko);
        LDSM_X4(bl0, bl1, bl2, bl3, b0b + LO_B + ko);
        LDSM_X4(bl4, bl5, bl6, bl7, b1b + LO_B + ko);

        MMA_BF16(acc[0], ah0, ah1, ah2, ah3, bh0, bh1);
        MMA_BF16(acc[1], ah0, ah1, ah2, ah3, bh2, bh3);
        MMA_BF16(acc[2], ah0, ah1, ah2, ah3, bh4, bh5);
        MMA_BF16(acc[3], ah0, ah1, ah2, ah3, bh6, bh7);
        MMA_BF16(acc[4], ah4, ah5, ah6, ah7, bh0, bh1);
        MMA_BF16(acc[5], ah4, ah5, ah6, ah7, bh2, bh3);
        MMA_BF16(acc[6], ah4, ah5, ah6, ah7, bh4, bh5);
        MMA_BF16(acc[7], ah4, ah5, ah6, ah7, bh6, bh7);

        MMA_BF16(acc[0], al0, al1, al2, al3, bh0, bh1);
        MMA_BF16(acc[1], al0, al1, al2, al3, bh2, bh3);
        MMA_BF16(acc[2], al0, al1, al2, al3, bh4, bh5);
        MMA_BF16(acc[3], al0, al1, al2, al3, bh6, bh7);
        MMA_BF16(acc[4], al4, al5, al6, al7, bh0, bh1);
        MMA_BF16(acc[5], al4, al5, al6, al7, bh2, bh3);
        MMA_BF16(acc[6], al4, al5, al6, al7, bh4, bh5);
        MMA_BF16(acc[7], al4, al5, al6, al7, bh6, bh7);

        MMA_BF16(acc[0], ah0, ah1, ah2, ah3, bl0, bl1);
        MMA_BF16(acc[1], ah0, ah1, ah2, ah3, bl2, bl3);
        MMA_BF16(acc[2], ah0, ah1, ah2, ah3, bl4, bl5);
        MMA_BF16(acc[3], ah0, ah1, ah2, ah3, bl6, bl7);
        MMA_BF16(acc[4], ah4, ah5, ah6, ah7, bl0, bl1);
        MMA_BF16(acc[5], ah4, ah5, ah6, ah7, bl2, bl3);
        MMA_BF16(acc[6], ah4, ah5, ah6, ah7, bl4, bl5);
        MMA_BF16(acc[7], ah4, ah5, ah6, ah7, bl6, bl7);
    }

    // ---- epilogue ----
    {
        const int g  = lane >> 2;
        const int qi = lane & 3;
        #pragma unroll
        for (int i = 0; i < 2; ++i) {
            const int orow0 = row_base + m0 + i * 16 + g;
            const int orow1 = orow0 + 8;
            #pragma unroll
            for (int j = 0; j < 4; ++j) {
                const int col = n0 + j * 8 + qi * 2;
                const float4 a = acc[i * 4 + j];
                float2 bb = *(const float2*)(bias + col);
                float2 v0 = make_float2(a.x + bb.x, a.y + bb.y);
                float2 v1 = make_float2(a.z + bb.x, a.w + bb.y);
                if (FIRST) {
                    v0.x = fmaxf(v0.x, 0.f); v0.y = fmaxf(v0.y, 0.f);
                    v1.x = fmaxf(v1.x, 0.f); v1.y = fmaxf(v1.y, 0.f);
                }
                if (orow0 < N_NODES) *(float2*)(Y + (size_t)orow0 * DIM + col) = v0;
                if (orow1 < N_NODES) *(float2*)(Y + (size_t)orow1 * DIM + col) = v1;
            }
        }
    }
}

// ---------------------------------------------------------------------------
extern "C" void kernel_launch(void* const* d_in, const int* in_sizes, int n_in,
                              void* d_out, int out_size)
{
    const float* x  = (const float*)d_in[0];
    const void*  ei = d_in[1];
    const float* W1 = (const float*)d_in[2];
    const float* b1 = (const float*)d_in[3];
    const float* W2 = (const float*)d_in[4];
    const float* b2 = (const float*)d_in[5];
    float*       out = (float*)d_out;

    cudaFuncSetAttribute(gemm_mma_kernel<true>,
                         cudaFuncAttributeMaxDynamicSharedMemorySize, SMEM_SZ);
    cudaFuncSetAttribute(gemm_mma_kernel<false>,
                         cudaFuncAttributeMaxDynamicSharedMemorySize, SMEM_SZ);

    __nv_bfloat16* wimg_d = nullptr;
    cudaGetSymbolAddress((void**)&wimg_d, g_wimg);
    const float* wimg0 = (const float*)wimg_d;
    const float* wimg1 = (const float*)(wimg_d + 2 * WTILE_ELEMS);

    // 0) setup: detect dtype + zero counts + W image prep (single launch)
    setup_kernel<<<SETUP_BLOCKS, 256>>>(ei, W1, W2);
    // 1) bucket fill (4 edges/thread)
    fill_kernel<<<(N_EDGES / 4 + 255) / 256, 256>>>(ei);
    // 2) h = relu(x W1^T + b1)
    gemm_mma_kernel<true><<<GBLOCKS, GTHREADS, SMEM_SZ>>>(x, wimg0, b1, nullptr);
    // 3) agg[n] = mean neighbor h (dedicated high-occupancy gather)
    gather_kernel<<<(N_NODES * 32 + 255) / 256, 256>>>();
    // 4) out = (h + agg) W2^T + b2
    gemm_mma_kernel<false><<<GBLOCKS, GTHREADS, SMEM_SZ>>>(nullptr, wimg1, b2, out);
}